// round 3
// baseline (speedup 1.0000x reference)
#include <cuda_runtime.h>
#include <cuda_fp16.h>
#include <cstdint>

// Problem constants
#define TOKENS 32768          // B*S = 16*2048
#define FDIM   1024
#define NQKV   3072
#define NHEAD  16
#define DHEAD  64

// ---------------------------------------------------------------------------
// Scratch (device globals; no allocations allowed)
// ---------------------------------------------------------------------------
__device__ __align__(16) half  g_X16 [(size_t)TOKENS * FDIM];   // x in fp16
__device__ __align__(16) half  g_Wqkv[(size_t)NQKV * FDIM];     // [N=3072, K=1024] transposed
__device__ __align__(16) half  g_Wo16[(size_t)FDIM * FDIM];     // [N=1024, K=1024] transposed
__device__ float               g_bqkv[NQKV];                    // packed biases
__device__ __align__(16) half  g_QKV [(size_t)TOKENS * NQKV];   // q,k,v per token
__device__ __align__(16) half  g_Attn[(size_t)TOKENS * FDIM];   // attention output
__device__ __align__(16) float g_Z   [(size_t)TOKENS * FDIM];   // pre-LN output

// ---------------------------------------------------------------------------
// PTX helpers
// ---------------------------------------------------------------------------
__device__ __forceinline__ void cp_async16(void* dst, const void* src){
    unsigned s = (unsigned)__cvta_generic_to_shared(dst);
    asm volatile("cp.async.cg.shared.global [%0], [%1], 16;\n" :: "r"(s), "l"(src));
}
__device__ __forceinline__ void cp_commit(){ asm volatile("cp.async.commit_group;\n"); }
template<int N>
__device__ __forceinline__ void cp_wait(){ asm volatile("cp.async.wait_group %0;\n" :: "n"(N)); }

__device__ __forceinline__ void ldsm_x4(uint32_t* r, uint32_t addr){
    asm volatile("ldmatrix.sync.aligned.m8n8.x4.shared.b16 {%0,%1,%2,%3}, [%4];\n"
        : "=r"(r[0]), "=r"(r[1]), "=r"(r[2]), "=r"(r[3]) : "r"(addr));
}
__device__ __forceinline__ void mma16816(float* c, const uint32_t* a, const uint32_t* b){
    asm volatile("mma.sync.aligned.m16n8k16.row.col.f32.f16.f16.f32 "
        "{%0,%1,%2,%3}, {%4,%5,%6,%7}, {%8,%9}, {%0,%1,%2,%3};\n"
        : "+f"(c[0]), "+f"(c[1]), "+f"(c[2]), "+f"(c[3])
        : "r"(a[0]), "r"(a[1]), "r"(a[2]), "r"(a[3]), "r"(b[0]), "r"(b[1]));
}

// ---------------------------------------------------------------------------
// Convert x fp32 -> fp16, and pack biases
// ---------------------------------------------------------------------------
__global__ void __launch_bounds__(256) convx_kernel(const float* __restrict__ x,
    const float* __restrict__ bq, const float* __restrict__ bk, const float* __restrict__ bv)
{
    const size_t n4 = (size_t)TOKENS * FDIM / 4;
    size_t gid = (size_t)blockIdx.x * blockDim.x + threadIdx.x;
    size_t stride = (size_t)gridDim.x * blockDim.x;
    for (size_t i = gid; i < n4; i += stride){
        float4 v = ((const float4*)x)[i];
        ((half2*)g_X16)[2*i]   = __floats2half2_rn(v.x, v.y);
        ((half2*)g_X16)[2*i+1] = __floats2half2_rn(v.z, v.w);
    }
    if (gid < NQKV){
        g_bqkv[gid] = (gid < 1024) ? bq[gid] : (gid < 2048) ? bk[gid - 1024] : bv[gid - 2048];
    }
}

// ---------------------------------------------------------------------------
// Tiled transpose: W[k][n] fp32 -> Wt[n][k] fp16.  z: 0..2 -> Wqkv rows, 3 -> Wo
// ---------------------------------------------------------------------------
__global__ void __launch_bounds__(256) transw_kernel(
    const float* __restrict__ Wq, const float* __restrict__ Wk,
    const float* __restrict__ Wv, const float* __restrict__ Wo)
{
    __shared__ float t[32][33];
    const int z = blockIdx.z;
    const float* src = (z == 0) ? Wq : (z == 1) ? Wk : (z == 2) ? Wv : Wo;
    const int k0 = blockIdx.y * 32, n0 = blockIdx.x * 32;
    const int tx = threadIdx.x, ty = threadIdx.y;   // 32 x 8
    #pragma unroll
    for (int i = 0; i < 4; ++i)
        t[ty + i * 8][tx] = src[(size_t)(k0 + ty + i * 8) * FDIM + n0 + tx];
    __syncthreads();
    half* dst = (z < 3) ? (g_Wqkv + (size_t)z * FDIM * FDIM) : g_Wo16;
    #pragma unroll
    for (int i = 0; i < 4; ++i)
        dst[(size_t)(n0 + ty + i * 8) * FDIM + k0 + tx] = __float2half_rn(t[tx][ty + i * 8]);
}

// ---------------------------------------------------------------------------
// HMMA GEMM: C[M,NTOT] = A[M,1024] * B[NTOT,1024]^T + bias
//   CTA tile 128x256, 8 warps (wm 0..1, wn 0..3), warp tile 64x64.
//   BK=64, 4-stage cp.async ring, one __syncthreads per k-block.
//   SMEM rows padded to 72 halfs (granule stride 9, coprime 8 -> conflict-free
//   ldmatrix). Both A (tokens) and B (weights, [N,K]) are K-major rows.
// MODE 0: A=g_X16, B=g_Wqkv, C=g_QKV (half), bias=g_bqkv
// MODE 1: A=g_Attn, B=g_Wo16, C=g_Z (float), bias=bias_ext
// ---------------------------------------------------------------------------
#define BM 128
#define BN 256
#define BK 64
#define SROW 72                       // padded row stride (halfs)
#define A_ST_BYTES (BM * SROW * 2)    // 18432
#define B_ST_BYTES (BN * SROW * 2)    // 36864
#define STAGE_BYTES (A_ST_BYTES + B_ST_BYTES)   // 55296
#define NSTAGES 4
#define NKBLK (FDIM / BK)             // 16
#define GEMM_DSMEM (NSTAGES * STAGE_BYTES)      // 221184

template<int MODE>
__global__ void __launch_bounds__(256, 1) gemm_hmma_kernel(const float* __restrict__ bias_ext)
{
    constexpr int NTOT = (MODE == 0) ? NQKV : FDIM;
    const half* __restrict__ A  = (MODE == 0) ? g_X16 : g_Attn;
    const half* __restrict__ Bw = (MODE == 0) ? g_Wqkv : g_Wo16;

    extern __shared__ __align__(16) half sm[];

    const int tid  = threadIdx.x;
    const int lane = tid & 31;
    const int wid  = tid >> 5;
    const int wm   = wid & 1;         // 0..1 -> 64-row slice
    const int wn   = wid >> 1;        // 0..3 -> 64-col slice
    const int m0 = blockIdx.y * BM;
    const int n0 = blockIdx.x * BN;

    const half* Abase = A  + (size_t)m0 * FDIM;
    const half* Bbase = Bw + (size_t)n0 * FDIM;

    float acc[4][8][4];
    #pragma unroll
    for (int mi = 0; mi < 4; ++mi)
        #pragma unroll
        for (int ni = 0; ni < 8; ++ni)
            #pragma unroll
            for (int t = 0; t < 4; ++t) acc[mi][ni][t] = 0.f;

    auto load_stage = [&](int s){
        const int buf = s & (NSTAGES - 1);
        half* as = sm + (size_t)buf * (STAGE_BYTES / 2);
        half* bs = as + (A_ST_BYTES / 2);
        const half* Asrc = Abase + s * BK;
        const half* Bsrc = Bbase + s * BK;
        // A: 128 rows x 8 chunks of 8 halfs = 1024 tasks
        #pragma unroll
        for (int i = 0; i < 4; ++i){
            int idx = tid + i * 256;
            int r = idx >> 3, c = idx & 7;
            cp_async16(as + r * SROW + c * 8, Asrc + (size_t)r * FDIM + c * 8);
        }
        // B: 256 rows x 8 chunks = 2048 tasks
        #pragma unroll
        for (int i = 0; i < 8; ++i){
            int idx = tid + i * 256;
            int r = idx >> 3, c = idx & 7;
            cp_async16(bs + r * SROW + c * 8, Bsrc + (size_t)r * FDIM + c * 8);
        }
        cp_commit();
    };

    // prologue: 3 stages in flight
    load_stage(0); load_stage(1); load_stage(2);

    // per-warp fragment base addresses (lane-dependent parts)
    const int a_row = wm * 64 + (lane & 15);           // + mi*16
    const int a_colb = (lane >> 4) << 3;               // + kk*16
    const int b_row = wn * 64 + (lane & 7) + ((lane >> 4) << 3);  // + ni*16
    const int b_colb = ((lane >> 3) & 1) << 3;         // + kk*16

    for (int s = 0; s < NKBLK; ++s){
        const int rem = (NKBLK - 1) - s;
        if (rem >= 2)      cp_wait<2>();
        else if (rem == 1) cp_wait<1>();
        else               cp_wait<0>();
        __syncthreads();

        if (s + 3 < NKBLK) load_stage(s + 3);

        const int buf = s & (NSTAGES - 1);
        const half* as = sm + (size_t)buf * (STAGE_BYTES / 2);
        const half* bs = as + (A_ST_BYTES / 2);
        const uint32_t aB = (uint32_t)__cvta_generic_to_shared(as);
        const uint32_t bB = (uint32_t)__cvta_generic_to_shared(bs);

        #pragma unroll
        for (int kk = 0; kk < 4; ++kk){
            const int k16 = kk * 16;
            uint32_t a[4][4], b[8][2];
            #pragma unroll
            for (int mi = 0; mi < 4; ++mi){
                uint32_t addr = aB + (uint32_t)(((a_row + mi * 16) * SROW + k16 + a_colb) * 2);
                ldsm_x4(&a[mi][0], addr);
            }
            #pragma unroll
            for (int nb = 0; nb < 4; ++nb){
                uint32_t addr = bB + (uint32_t)(((b_row + nb * 16) * SROW + k16 + b_colb) * 2);
                uint32_t r[4];
                ldsm_x4(r, addr);
                b[nb * 2][0] = r[0];     b[nb * 2][1] = r[1];
                b[nb * 2 + 1][0] = r[2]; b[nb * 2 + 1][1] = r[3];
            }
            #pragma unroll
            for (int mi = 0; mi < 4; ++mi)
                #pragma unroll
                for (int ni = 0; ni < 8; ++ni)
                    mma16816(acc[mi][ni], a[mi], b[ni]);
        }
    }

    // epilogue: +bias, store
    const float* bias = (MODE == 0) ? g_bqkv : bias_ext;
    #pragma unroll
    for (int mi = 0; mi < 4; ++mi){
        #pragma unroll
        for (int ni = 0; ni < 8; ++ni){
            int r = m0 + wm * 64 + mi * 16 + (lane >> 2);
            int c = n0 + wn * 64 + ni * 8 + ((lane & 3) << 1);
            float b0 = bias[c], b1 = bias[c + 1];
            float v0 = acc[mi][ni][0] + b0, v1 = acc[mi][ni][1] + b1;
            float v2 = acc[mi][ni][2] + b0, v3 = acc[mi][ni][3] + b1;
            if constexpr (MODE == 0){
                *(half2*)(g_QKV + (size_t)r * NTOT + c)       = __floats2half2_rn(v0, v1);
                *(half2*)(g_QKV + (size_t)(r + 8) * NTOT + c) = __floats2half2_rn(v2, v3);
            } else {
                *(float2*)(g_Z + (size_t)r * NTOT + c)       = make_float2(v0, v1);
                *(float2*)(g_Z + (size_t)(r + 8) * NTOT + c) = make_float2(v2, v3);
            }
        }
    }
}

// ---------------------------------------------------------------------------
// Per-token cross-head attention. 1 warp per token, 8 tokens per block.
// ---------------------------------------------------------------------------
__global__ void __launch_bounds__(256) attn_kernel(){
    __shared__ half sq[8][NQKV];   // 48 KB
    const int tid = threadIdx.x, lane = tid & 31, w = tid >> 5;
    const size_t tok0 = (size_t)blockIdx.x * 8;

    const float4* src = (const float4*)(g_QKV + tok0 * NQKV);
    float4* dstv = (float4*)&sq[0][0];
    #pragma unroll
    for (int i = 0; i < 12; ++i) dstv[tid + i * 256] = src[tid + i * 256];
    __syncthreads();

    const half2* q2 = (const half2*)&sq[w][0];
    const half2* k2 = (const half2*)&sq[w][1024];
    const half2* v2 = (const half2*)&sq[w][2048];
    const int h  = lane >> 1;
    const int gb = (lane & 1) << 3;

    float2 qr[32];
    #pragma unroll
    for (int j = 0; j < 32; ++j){
        int d = (j + h) & 31;
        qr[j] = __half22float2(q2[h * 32 + d]);
    }

    float e[8];
    #pragma unroll
    for (int gi = 0; gi < 8; ++gi){
        int g = gb + gi;
        float a = 0.f;
        #pragma unroll
        for (int j = 0; j < 32; ++j){
            int d = (j + h) & 31;
            float2 kf = __half22float2(k2[g * 32 + d]);
            a += qr[j].x * kf.x + qr[j].y * kf.y;
        }
        e[gi] = a * 0.125f;
    }

    float m = e[0];
    #pragma unroll
    for (int gi = 1; gi < 8; ++gi) m = fmaxf(m, e[gi]);
    m = fmaxf(m, __shfl_xor_sync(0xffffffffu, m, 1));
    float ssum = 0.f;
    #pragma unroll
    for (int gi = 0; gi < 8; ++gi){ e[gi] = __expf(e[gi] - m); ssum += e[gi]; }
    ssum += __shfl_xor_sync(0xffffffffu, ssum, 1);
    float inv = 1.f / ssum;

    float2 o[32];
    #pragma unroll
    for (int j = 0; j < 32; ++j) o[j] = make_float2(0.f, 0.f);
    #pragma unroll
    for (int gi = 0; gi < 8; ++gi){
        float p = e[gi] * inv;
        int g = gb + gi;
        #pragma unroll
        for (int j = 0; j < 32; ++j){
            int d = (j + h) & 31;
            float2 vf = __half22float2(v2[g * 32 + d]);
            o[j].x += p * vf.x; o[j].y += p * vf.y;
        }
    }
    #pragma unroll
    for (int j = 0; j < 32; ++j){
        o[j].x += __shfl_xor_sync(0xffffffffu, o[j].x, 1);
        o[j].y += __shfl_xor_sync(0xffffffffu, o[j].y, 1);
    }
    __syncwarp();

    half2* outs = (half2*)&sq[w][0];
    if ((lane & 1) == 0){
        #pragma unroll
        for (int j = 0; j < 32; ++j){
            int d = (j + h) & 31;
            outs[h * 32 + d] = __floats2half2_rn(o[j].x, o[j].y);
        }
    }
    __syncthreads();

    float4* gout = (float4*)(g_Attn + tok0 * FDIM);
    #pragma unroll
    for (int i = 0; i < 4; ++i){
        int c = tid + i * 256;
        int tw = c >> 7, off = c & 127;
        gout[c] = *(const float4*)(&sq[tw][off * 8]);
    }
}

// ---------------------------------------------------------------------------
// LayerNorm over F=1024, one block per row
// ---------------------------------------------------------------------------
__global__ void __launch_bounds__(256) ln_kernel(const float* __restrict__ gamma,
                                                 const float* __restrict__ beta,
                                                 float* __restrict__ out)
{
    const int row = blockIdx.x, t = threadIdx.x, lane = t & 31, wid = t >> 5;
    float4 v = ((const float4*)(g_Z + (size_t)row * FDIM))[t];
    float s = v.x + v.y + v.z + v.w;
    float q = v.x * v.x + v.y * v.y + v.z * v.z + v.w * v.w;
    #pragma unroll
    for (int o = 16; o > 0; o >>= 1){
        s += __shfl_xor_sync(0xffffffffu, s, o);
        q += __shfl_xor_sync(0xffffffffu, q, o);
    }
    __shared__ float ws[8], wq[8], mv[2];
    if (lane == 0){ ws[wid] = s; wq[wid] = q; }
    __syncthreads();
    if (t == 0){
        float S = 0.f, Q = 0.f;
        #pragma unroll
        for (int i = 0; i < 8; ++i){ S += ws[i]; Q += wq[i]; }
        float mean = S * (1.f / 1024.f);
        float var  = Q * (1.f / 1024.f) - mean * mean;
        mv[0] = mean; mv[1] = rsqrtf(var + 1e-5f);
    }
    __syncthreads();
    float mean = mv[0], rstd = mv[1];
    float4 g4 = ((const float4*)gamma)[t];
    float4 b4 = ((const float4*)beta)[t];
    float4 r;
    r.x = (v.x - mean) * rstd * g4.x + b4.x;
    r.y = (v.y - mean) * rstd * g4.y + b4.y;
    r.z = (v.z - mean) * rstd * g4.z + b4.z;
    r.w = (v.w - mean) * rstd * g4.w + b4.w;
    ((float4*)(out + (size_t)row * FDIM))[t] = r;
}

// ---------------------------------------------------------------------------
// Launch
// ---------------------------------------------------------------------------
extern "C" void kernel_launch(void* const* d_in, const int* in_sizes, int n_in,
                              void* d_out, int out_size)
{
    (void)in_sizes; (void)n_in; (void)out_size;
    const float* x     = (const float*)d_in[0];
    const float* Wq    = (const float*)d_in[1];
    const float* bq    = (const float*)d_in[2];
    const float* Wk    = (const float*)d_in[3];
    const float* bk    = (const float*)d_in[4];
    const float* Wv    = (const float*)d_in[5];
    const float* bv    = (const float*)d_in[6];
    const float* Wo    = (const float*)d_in[7];
    const float* bo    = (const float*)d_in[8];
    const float* gamma = (const float*)d_in[9];
    const float* beta  = (const float*)d_in[10];
    float* out = (float*)d_out;

    static int configured = 0;
    cudaFuncSetAttribute(gemm_hmma_kernel<0>, cudaFuncAttributeMaxDynamicSharedMemorySize, GEMM_DSMEM);
    cudaFuncSetAttribute(gemm_hmma_kernel<1>, cudaFuncAttributeMaxDynamicSharedMemorySize, GEMM_DSMEM);
    (void)configured;

    convx_kernel<<<4096, 256>>>(x, bq, bk, bv);
    transw_kernel<<<dim3(32, 32, 4), dim3(32, 8)>>>(Wq, Wk, Wv, Wo);
    gemm_hmma_kernel<0><<<dim3(NQKV / BN, TOKENS / BM), 256, GEMM_DSMEM>>>(nullptr);
    attn_kernel<<<TOKENS / 8, 256>>>();
    gemm_hmma_kernel<1><<<dim3(FDIM / BN, TOKENS / BM), 256, GEMM_DSMEM>>>(bo);
    ln_kernel<<<TOKENS, 256>>>(gamma, beta, out);
}